// round 13
// baseline (speedup 1.0000x reference)
#include <cuda_runtime.h>
#include <cuda_bf16.h>

// RotatedIoULoss: per-pair rotated-box IoU, loss = mean(-log(max(iou,1e-6))).
//
// Target-local-frame slab clipping with slope sharing (2 RCPs per item) and
// inv-slope vertex tags (see per-item function). 2 items per thread (ILP-2):
// two independent dependency chains interleave in the scoreboard, hiding
// LDL/MUFU latency that a single chain exposes.
//
// Single kernel: block partial sums + threadfence/atomic-counter last-block
// final reduction (fixed order -> deterministic; counter self-resets for
// graph replay). Graph-capturable, allocation-free.

#define THREADS 256
#define ITEMS_PER_THREAD 2
#define MAX_BLOCKS 4096

__device__ float g_block_sums[MAX_BLOCKS];
__device__ unsigned int g_done_count;  // zero-init; reset by last block

struct __align__(8) Pt { float x, y; };

// Per-item loss. Logic identical to the audited R6 kernel body.
static __device__ __forceinline__ float item_loss(
    const float* __restrict__ pred, const float* __restrict__ target, int i) {
    const float px = pred[i * 5 + 0], py = pred[i * 5 + 1];
    const float pw = pred[i * 5 + 2], ph = pred[i * 5 + 3];
    const float pa = pred[i * 5 + 4];
    const float tx = target[i * 5 + 0], ty = target[i * 5 + 1];
    const float tw = target[i * 5 + 2], th = target[i * 5 + 3];
    const float ta = target[i * 5 + 4];

    // Target local frame.
    float st, ct;
    __sincosf(ta, &st, &ct);
    const float dx = px - tx, dy = py - ty;
    const float lx =  dx * ct + dy * st;
    const float ly = -dx * st + dy * ct;

    // Pred corners (CCW) in that frame; relative rotation pa-ta.
    float sd, cd;
    __sincosf(pa - ta, &sd, &cd);
    const float hwp = 0.5f * pw, hhp = 0.5f * ph;
    const float cx = cd * hwp, sx = sd * hwp;
    const float cy = cd * hhp, sy = sd * hhp;

    Pt c0, c1, c2, c3;
    c0.x = lx - cx + sy;  c0.y = ly - sx - cy;
    c1.x = lx + cx + sy;  c1.y = ly + sx - cy;
    c2.x = lx + cx - sy;  c2.y = ly + sx + cy;
    c3.x = lx - cx - sy;  c3.y = ly - sx + cy;

    const float hwt = 0.5f * tw, hht = 0.5f * th;

    // Two slope reciprocals serve every intersection this item needs.
    const float rs = __fdividef(1.f, sd);
    const float rc = __fdividef(1.f, cd);
    // type0 = edges c0->c1 / c2->c3 (delta ~ (cd,sd));
    // type1 = edges c1->c2 / c3->c0 (delta ~ (-sd,cd)).
    const float slopeA0 = sd * rc;    // dy/dx, type0
    const float slopeA1 = -cd * rs;   // dy/dx, type1
    const float is0 = cd * rs;        // dx/dy, type0
    const float is1 = -sd * rc;       // dx/dy, type1

    // ---- Pass A: clip by x-slab |x|<=hwt (registers -> b, tags bt) ----
    Pt b[8];
    float bt[8];
    int m = 0;
    {
        Pt cs[4] = {c0, c1, c2, c3};
        Pt P = c3;
        bool il_p = (P.x >= -hwt);
        bool ir_p = (P.x <=  hwt);
        #pragma unroll
        for (int k = 0; k < 4; ++k) {
            // Edge P->C: k even => type1 (c3->c0, c1->c2), odd => type0.
            Pt C = cs[k];
            bool il_c = (C.x >= -hwt);
            bool ir_c = (C.x <=  hwt);
            bool inP = il_p && ir_p;

            const float slope = (k & 1) ? slopeA0 : slopeA1;
            const float istag = (k & 1) ? is0 : is1;

            b[m] = P; bt[m] = istag;      // P's outgoing = this edge
            m += (int)inP;

            float yl = fmaf(-hwt - P.x, slope, P.y);
            float yr = fmaf( hwt - P.x, slope, P.y);
            Pt pl; pl.x = -hwt; pl.y = yl;
            Pt pr; pr.x =  hwt; pr.y = yr;

            bool cl = (il_p != il_c);
            bool cr = (ir_p != ir_c);
            bool both = cl && cr;
            bool lfirst = (C.x > P.x);    // moving right: left line first

            Pt pA = both ? (lfirst ? pl : pr) : (cl ? pl : pr);
            Pt pB = lfirst ? pr : pl;

            b[m] = pA; bt[m] = inP ? 0.f : istag;  // exit -> chord tag 0
            m += (int)(cl || cr);
            b[m] = pB; bt[m] = 0.f;                // 2nd cross is an exit
            m += (int)both;

            P = C; il_p = il_c; ir_p = ir_c;
        }
    }

    // ---- Pass B: clip by y-slab |y|<=hht (b -> a), tag-driven ----
    Pt a[10];
    int mo = 0;
    if (m >= 3) {
        Pt P = b[m - 1];
        float tP = bt[m - 1];
        bool ib_p = (P.y >= -hht);
        bool it_p = (P.y <=  hht);
        #pragma unroll 1
        for (int k = 0; k < m; ++k) {
            Pt C = b[k];
            float tC = bt[k];
            bool ib_c = (C.y >= -hht);
            bool it_c = (C.y <=  hht);
            bool inP = ib_p && it_p;

            a[mo] = P;
            mo += (int)inP;

            // Crossings via carried inv-slope (chords: tP=0 -> x=P.x).
            float xb = fmaf(-hht - P.y, tP, P.x);
            float xt = fmaf( hht - P.y, tP, P.x);
            Pt pb; pb.x = xb; pb.y = -hht;
            Pt pt; pt.x = xt; pt.y =  hht;

            bool cb = (ib_p != ib_c);
            bool ctp = (it_p != it_c);
            bool both = cb && ctp;
            bool bfirst = (C.y > P.y);    // moving up: bottom line first

            Pt pA = both ? (bfirst ? pb : pt) : (cb ? pb : pt);
            Pt pB = bfirst ? pt : pb;

            a[mo] = pA;  mo += (int)(cb || ctp);
            a[mo] = pB;  mo += (int)both;

            P = C; tP = tC; ib_p = ib_c; it_p = it_c;
        }
    }

    // ---- Shoelace over a[0..mo) ----
    float s2 = 0.f;
    if (mo >= 3) {
        Pt P = a[mo - 1];
        #pragma unroll 1
        for (int k = 0; k < mo; ++k) {
            Pt C = a[k];
            s2 = fmaf(P.x, C.y, s2);
            s2 = fmaf(-P.y, C.x, s2);
            P = C;
        }
    }

    const float area_i = 0.5f * fabsf(s2);
    const float a1 = pw * ph;
    const float a2 = tw * th;
    const float denom = fmaxf(a1 + a2 - area_i, 1e-10f);
    float iou = fmaxf(__fdividef(area_i, denom), 1e-6f);
    return -__logf(iou);
}

__global__ void __launch_bounds__(THREADS)
rot_iou_loss_kernel(const float* __restrict__ pred,
                    const float* __restrict__ target,
                    int n, float inv_n, float* __restrict__ out) {
    const int stride = gridDim.x * blockDim.x;

    // Two independent accumulator chains per thread (ILP-2).
    float acc0 = 0.f, acc1 = 0.f;

    for (int i = blockIdx.x * blockDim.x + threadIdx.x; i < n;
         i += stride * ITEMS_PER_THREAD) {
        const int i1 = i + stride;
        // Chain 0 and chain 1 are fully independent; the compiler interleaves
        // their long-latency ops (sincos, LDL) in the scoreboard.
        acc0 += item_loss(pred, target, i);
        if (i1 < n) acc1 += item_loss(pred, target, i1);
    }
    float acc = acc0 + acc1;

    // ---- Block reduction ----
    __shared__ float sh[THREADS];
    __shared__ int s_last;
    sh[threadIdx.x] = acc;
    __syncthreads();
    #pragma unroll
    for (int k = THREADS / 2; k > 32; k >>= 1) {
        if (threadIdx.x < k) sh[threadIdx.x] += sh[threadIdx.x + k];
        __syncthreads();
    }
    if (threadIdx.x < 32) {
        float v = sh[threadIdx.x] + sh[threadIdx.x + 32];
        #pragma unroll
        for (int o = 16; o > 0; o >>= 1)
            v += __shfl_down_sync(0xffffffffu, v, o);
        if (threadIdx.x == 0) {
            g_block_sums[blockIdx.x] = v;
            __threadfence();
            unsigned int old = atomicAdd(&g_done_count, 1u);
            s_last = (old == gridDim.x - 1) ? 1 : 0;
        }
    }
    __syncthreads();

    // ---- Last block: final reduction (fixed order -> deterministic) ----
    if (s_last) {
        float s = 0.f;
        for (int j = threadIdx.x; j < (int)gridDim.x; j += THREADS)
            s += g_block_sums[j];
        sh[threadIdx.x] = s;
        __syncthreads();
        #pragma unroll
        for (int k = THREADS / 2; k > 32; k >>= 1) {
            if (threadIdx.x < k) sh[threadIdx.x] += sh[threadIdx.x + k];
            __syncthreads();
        }
        if (threadIdx.x < 32) {
            float v = sh[threadIdx.x] + sh[threadIdx.x + 32];
            #pragma unroll
            for (int o = 16; o > 0; o >>= 1)
                v += __shfl_down_sync(0xffffffffu, v, o);
            if (threadIdx.x == 0) {
                out[0] = v * inv_n;
                g_done_count = 0;   // reset for next graph replay
            }
        }
    }
}

extern "C" void kernel_launch(void* const* d_in, const int* in_sizes, int n_in,
                              void* d_out, int out_size) {
    const float* pred   = (const float*)d_in[0];
    const float* target = (const float*)d_in[1];
    float* out = (float*)d_out;

    const int n = in_sizes[0] / 5;
    const int per_block = THREADS * ITEMS_PER_THREAD;
    int blocks = (n + per_block - 1) / per_block;
    if (blocks > MAX_BLOCKS) blocks = MAX_BLOCKS;
    if (blocks < 1) blocks = 1;

    rot_iou_loss_kernel<<<blocks, THREADS>>>(pred, target, n,
                                             1.0f / (float)n, out);
}